// round 5
// baseline (speedup 1.0000x reference)
#include <cuda_runtime.h>
#include <cuda_bf16.h>

// Problem constants (fixed by dataset)
#define NN 50000
#define DD 128
#define EE 800000
#define RR 2
#define LL 2
#define GG 64
#define CC 8

// Scratch (no allocations allowed -> __device__ globals).
// NOTE: these symbols must NEVER be referenced from host code (host shadow
// trap + ATS on GB300 silently reads host zeros). Device-code only.
__device__ float g_deg[RR * NN];
__device__ float g_inv[RR * NN];
__device__ float g_xw[RR * NN * DD];   // per-layer: xw for both relations
__device__ float g_out[NN * DD];       // layer output accumulator
__device__ float g_h[NN * DD];         // hidden after relu
__device__ float g_sums[GG * DD];
__device__ float g_cnt[GG];

// ---------------------------------------------------------------------------
// zero scratch that gets atomically accumulated
__global__ void k_zero() {
    int t = blockIdx.x * blockDim.x + threadIdx.x;
    if (t < RR * NN) g_deg[t] = 0.f;
    if (t < GG * DD) g_sums[t] = 0.f;
    if (t < GG) g_cnt[t] = 0.f;
}

// degree count (dst side), per relation
__global__ void k_deg(const int* __restrict__ edges) {
    int t = blockIdx.x * blockDim.x + threadIdx.x;
    if (t >= RR * EE) return;
    int r = (t >= EE) ? 1 : 0;
    int e = t - r * EE;
    int dst = edges[r * 2 * EE + EE + e];
    atomicAdd(&g_deg[r * NN + dst], 1.f);
}

__global__ void k_inv() {
    int t = blockIdx.x * blockDim.x + threadIdx.x;
    if (t >= RR * NN) return;
    g_inv[t] = rsqrtf(g_deg[t] + 1.f);
}

// ---------------------------------------------------------------------------
// GEMM: XW[r] = A (N x 128) @ W[l,r] (128 x 128)
// blockDim 256, each block: 64 rows x 128 cols. warp w -> rows w*8..w*8+7,
// lane -> 4 cols. Input selected in DEVICE code: x (layer 0) or g_h (layer 1).
__global__ void k_gemm(const float* __restrict__ x_in, int use_h,
                       const float* __restrict__ Wl) {
    const float* __restrict__ A = use_h ? g_h : x_in;
    const int r = blockIdx.y;
    const float* __restrict__ Wr = Wl + r * DD * DD;
    float* __restrict__ out = g_xw + (size_t)r * NN * DD;
    const int row0 = blockIdx.x * 64;
    __shared__ float sA[64 * DD];
    const int tid = threadIdx.x;

#pragma unroll
    for (int i = 0; i < 32; i++) {
        int idx = tid + i * 256;          // 0..8191
        int rr = idx >> 7, cc = idx & 127;
        int row = row0 + rr;
        sA[idx] = (row < NN) ? A[row * DD + cc] : 0.f;
    }
    __syncthreads();

    const int lane = tid & 31;
    const int w = tid >> 5;
    float4 acc[8];
#pragma unroll
    for (int i = 0; i < 8; i++) acc[i] = make_float4(0.f, 0.f, 0.f, 0.f);

    const float* __restrict__ wp = Wr + lane * 4;
#pragma unroll 4
    for (int k = 0; k < DD; k++) {
        float4 wv = *(const float4*)(wp + k * DD);
#pragma unroll
        for (int rr = 0; rr < 8; rr++) {
            float a = sA[(w * 8 + rr) * DD + k];
            acc[rr].x = fmaf(a, wv.x, acc[rr].x);
            acc[rr].y = fmaf(a, wv.y, acc[rr].y);
            acc[rr].z = fmaf(a, wv.z, acc[rr].z);
            acc[rr].w = fmaf(a, wv.w, acc[rr].w);
        }
    }
#pragma unroll
    for (int rr = 0; rr < 8; rr++) {
        int row = row0 + w * 8 + rr;
        if (row < NN)
            *(float4*)&out[row * DD + lane * 4] = acc[rr];
    }
}

// ---------------------------------------------------------------------------
// init output with self-loop messages + biases (both relations)
__global__ void k_init_out(const float* __restrict__ bvec) {
    int t = blockIdx.x * blockDim.x + threadIdx.x;
    if (t >= NN * DD) return;
    int n = t >> 7, c = t & 127;
    float i0 = g_inv[n];
    float i1 = g_inv[NN + n];
    g_out[t] = g_xw[t] * (i0 * i0) + g_xw[NN * DD + t] * (i1 * i1)
             + bvec[c] + bvec[DD + c];
}

// edge scatter: one warp per edge, 4 floats per lane; atomic accumulate at dst
__global__ void k_scatter(const int* __restrict__ edges) {
    long long t = (long long)blockIdx.x * blockDim.x + threadIdx.x;
    int eg = (int)(t >> 5);
    if (eg >= RR * EE) return;
    int lane = (int)(t & 31);
    int r = (eg >= EE) ? 1 : 0;
    int e = eg - r * EE;
    const int* er = edges + r * 2 * EE;
    int src = er[e];
    int dst = er[EE + e];
    const float* invr = g_inv + r * NN;
    float norm = invr[src] * invr[dst];
    float4 v = *(const float4*)&g_xw[(size_t)r * NN * DD + src * DD + lane * 4];
    float* o = &g_out[dst * DD + lane * 4];
    atomicAdd(o + 0, v.x * norm);
    atomicAdd(o + 1, v.y * norm);
    atomicAdd(o + 2, v.z * norm);
    atomicAdd(o + 3, v.w * norm);
}

__global__ void k_relu() {
    int t = blockIdx.x * blockDim.x + threadIdx.x;
    if (t >= NN * DD) return;
    g_h[t] = fmaxf(g_out[t], 0.f);
}

// ---------------------------------------------------------------------------
// global mean pool (atomic accumulate) + final tiny linear
__global__ void k_pool(const int* __restrict__ batch) {
    int t = blockIdx.x * blockDim.x + threadIdx.x;
    if (t >= NN * DD) return;
    int n = t >> 7, c = t & 127;
    int g = batch[n];
    atomicAdd(&g_sums[g * DD + c], g_out[t]);
    if (c == 0) atomicAdd(&g_cnt[g], 1.f);
}

__global__ void k_final(const float* __restrict__ lw, const float* __restrict__ lb,
                        float* __restrict__ out) {
    int t = threadIdx.x;          // 512 = G*C
    int g = t >> 3, c = t & 7;
    float inv = 1.f / fmaxf(g_cnt[g], 1.f);
    float acc = lb[c];
#pragma unroll 8
    for (int d = 0; d < DD; d++)
        acc = fmaf(g_sums[g * DD + d] * inv, lw[d * CC + c], acc);
    out[g * CC + c] = acc;
}

// ---------------------------------------------------------------------------
extern "C" void kernel_launch(void* const* d_in, const int* in_sizes, int n_in,
                              void* d_out, int out_size) {
    // Bind inputs by UNIQUE element counts (robust to metadata ordering):
    //   x:6400000  W:65536  b:512  lin_w:1024  lin_b:8  edges:3200000  batch:50000
    const float* x = nullptr;
    const float* W = nullptr;
    const float* b = nullptr;
    const float* lin_w = nullptr;
    const float* lin_b = nullptr;
    const int* edges = nullptr;
    const int* batch = nullptr;
    for (int i = 0; i < n_in; i++) {
        switch (in_sizes[i]) {
            case NN * DD:            x     = (const float*)d_in[i]; break; // 6,400,000
            case LL * RR * DD * DD:  W     = (const float*)d_in[i]; break; // 65,536
            case LL * RR * DD:       b     = (const float*)d_in[i]; break; // 512
            case DD * CC:            lin_w = (const float*)d_in[i]; break; // 1,024
            case CC:                 lin_b = (const float*)d_in[i]; break; // 8
            case RR * 2 * EE:        edges = (const int*)d_in[i];   break; // 3,200,000
            case NN:                 batch = (const int*)d_in[i];   break; // 50,000
            default: break;
        }
    }
    float* out = (float*)d_out;                   // [G, C]

    const int TB = 256;

    // normalization (recomputed every call; no caching)
    k_zero<<<(RR * NN + TB - 1) / TB, TB>>>();
    k_deg<<<(RR * EE + TB - 1) / TB, TB>>>(edges);
    k_inv<<<(RR * NN + TB - 1) / TB, TB>>>();

    const int gemm_grid = (NN + 63) / 64;
    const long long scat_threads = (long long)RR * EE * 32;
    const int scat_blocks = (int)((scat_threads + TB - 1) / TB);
    const int nd_blocks = (NN * DD + TB - 1) / TB;

    for (int l = 0; l < LL; l++) {
        k_gemm<<<dim3(gemm_grid, RR), 256>>>(x, l > 0 ? 1 : 0,
                                             W + (size_t)l * RR * DD * DD);
        k_init_out<<<nd_blocks, TB>>>(b + (size_t)l * RR * DD);
        k_scatter<<<scat_blocks, TB>>>(edges);
        if (l < LL - 1) {
            k_relu<<<nd_blocks, TB>>>();
        }
    }

    k_pool<<<nd_blocks, TB>>>(batch);
    k_final<<<1, GG * CC>>>(lin_w, lin_b, out);
}

// round 6
// speedup vs baseline: 2.5080x; 2.5080x over previous
#include <cuda_runtime.h>
#include <cuda_bf16.h>

// Problem constants (fixed by dataset)
#define NN 50000
#define DD 128
#define EE 800000
#define RR 2
#define LL 2
#define GG 64
#define CC 8

// Scratch (no allocations allowed -> __device__ globals).
// NOTE: never referenced from host code (host-shadow + ATS trap on GB300).
__device__ float g_deg[RR * NN];
__device__ float g_inv[RR * NN];
__device__ float g_xw[RR * NN * DD];   // per-layer: xw for both relations
__device__ float g_out[NN * DD];       // layer output accumulator
__device__ float g_h[NN * DD];         // hidden after relu
__device__ float g_sums[GG * DD];
__device__ float g_cnt[GG];

__device__ __forceinline__ void red_add_v4(float* addr, float a, float b,
                                           float c, float d) {
    asm volatile("red.global.add.v4.f32 [%0], {%1, %2, %3, %4};"
                 :: "l"(addr), "f"(a), "f"(b), "f"(c), "f"(d) : "memory");
}

// ---------------------------------------------------------------------------
// zero scratch that gets atomically accumulated
__global__ void k_zero() {
    int t = blockIdx.x * blockDim.x + threadIdx.x;
    if (t < RR * NN) g_deg[t] = 0.f;
    if (t < GG * DD) g_sums[t] = 0.f;
    if (t < GG) g_cnt[t] = 0.f;
}

// degree count (dst side), per relation
__global__ void k_deg(const int* __restrict__ edges) {
    int t = blockIdx.x * blockDim.x + threadIdx.x;
    if (t >= RR * EE) return;
    int r = (t >= EE) ? 1 : 0;
    int e = t - r * EE;
    int dst = edges[r * 2 * EE + EE + e];
    atomicAdd(&g_deg[r * NN + dst], 1.f);
}

__global__ void k_inv() {
    int t = blockIdx.x * blockDim.x + threadIdx.x;
    if (t >= RR * NN) return;
    g_inv[t] = rsqrtf(g_deg[t] + 1.f);
}

// ---------------------------------------------------------------------------
// GEMM: XW[r] = A (N x 128) @ W[l,r] (128 x 128)
// blockDim 256; each block: 64 rows x 128 cols. warp w -> rows w*8..w*8+7,
// lane -> 4 cols. Input selected in DEVICE code: x (layer 0) or g_h (layer 1).
__global__ void k_gemm(const float* __restrict__ x_in, int use_h,
                       const float* __restrict__ Wl) {
    const float* __restrict__ A = use_h ? g_h : x_in;
    const int r = blockIdx.y;
    const float* __restrict__ Wr = Wl + r * DD * DD;
    float* __restrict__ out = g_xw + (size_t)r * NN * DD;
    const int row0 = blockIdx.x * 64;
    __shared__ float sA[64 * DD];
    const int tid = threadIdx.x;

#pragma unroll
    for (int i = 0; i < 32; i++) {
        int idx = tid + i * 256;          // 0..8191
        int rr = idx >> 7, cc = idx & 127;
        int row = row0 + rr;
        sA[idx] = (row < NN) ? A[row * DD + cc] : 0.f;
    }
    __syncthreads();

    const int lane = tid & 31;
    const int w = tid >> 5;
    float4 acc[8];
#pragma unroll
    for (int i = 0; i < 8; i++) acc[i] = make_float4(0.f, 0.f, 0.f, 0.f);

    const float* __restrict__ wp = Wr + lane * 4;
#pragma unroll 4
    for (int k = 0; k < DD; k++) {
        float4 wv = *(const float4*)(wp + k * DD);
#pragma unroll
        for (int rr = 0; rr < 8; rr++) {
            float a = sA[(w * 8 + rr) * DD + k];
            acc[rr].x = fmaf(a, wv.x, acc[rr].x);
            acc[rr].y = fmaf(a, wv.y, acc[rr].y);
            acc[rr].z = fmaf(a, wv.z, acc[rr].z);
            acc[rr].w = fmaf(a, wv.w, acc[rr].w);
        }
    }
#pragma unroll
    for (int rr = 0; rr < 8; rr++) {
        int row = row0 + w * 8 + rr;
        if (row < NN)
            *(float4*)&out[row * DD + lane * 4] = acc[rr];
    }
}

// ---------------------------------------------------------------------------
// init output with self-loop messages + biases (both relations)
__global__ void k_init_out(const float* __restrict__ bvec) {
    int t = blockIdx.x * blockDim.x + threadIdx.x;
    if (t >= NN * DD) return;
    int n = t >> 7, c = t & 127;
    float i0 = g_inv[n];
    float i1 = g_inv[NN + n];
    g_out[t] = g_xw[t] * (i0 * i0) + g_xw[NN * DD + t] * (i1 * i1)
             + bvec[c] + bvec[DD + c];
}

// edge scatter: one warp per edge; each lane does ONE red.global.add.v4.f32
// (4x fewer LTS atomic ops than scalar atomicAdd)
__global__ void k_scatter(const int* __restrict__ edges) {
    long long t = (long long)blockIdx.x * blockDim.x + threadIdx.x;
    int eg = (int)(t >> 5);
    if (eg >= RR * EE) return;
    int lane = (int)(t & 31);
    int r = (eg >= EE) ? 1 : 0;
    int e = eg - r * EE;
    const int* er = edges + r * 2 * EE;
    int src = er[e];
    int dst = er[EE + e];
    const float* invr = g_inv + r * NN;
    float norm = invr[src] * invr[dst];
    float4 v = *(const float4*)&g_xw[(size_t)r * NN * DD + src * DD + lane * 4];
    float* o = &g_out[dst * DD + lane * 4];
    red_add_v4(o, v.x * norm, v.y * norm, v.z * norm, v.w * norm);
}

__global__ void k_relu() {
    int t = blockIdx.x * blockDim.x + threadIdx.x;
    if (t >= NN * DD) return;
    g_h[t] = fmaxf(g_out[t], 0.f);
}

// ---------------------------------------------------------------------------
// global mean pool: v4 reductions, 4 floats per thread
__global__ void k_pool(const int* __restrict__ batch) {
    int t = blockIdx.x * blockDim.x + threadIdx.x;     // NN*DD/4 threads
    if (t >= NN * (DD / 4)) return;
    int n = t >> 5;             // node
    int c4 = (t & 31) * 4;      // column group
    int g = batch[n];
    float4 v = *(const float4*)&g_out[n * DD + c4];
    red_add_v4(&g_sums[g * DD + c4], v.x, v.y, v.z, v.w);
    if (c4 == 0) atomicAdd(&g_cnt[g], 1.f);
}

__global__ void k_final(const float* __restrict__ lw, const float* __restrict__ lb,
                        float* __restrict__ out) {
    int t = threadIdx.x;          // 512 = G*C
    int g = t >> 3, c = t & 7;
    float inv = 1.f / fmaxf(g_cnt[g], 1.f);
    float acc = lb[c];
#pragma unroll 8
    for (int d = 0; d < DD; d++)
        acc = fmaf(g_sums[g * DD + d] * inv, lw[d * CC + c], acc);
    out[g * CC + c] = acc;
}

// ---------------------------------------------------------------------------
extern "C" void kernel_launch(void* const* d_in, const int* in_sizes, int n_in,
                              void* d_out, int out_size) {
    // Bind inputs by UNIQUE element counts (robust to metadata ordering):
    const float* x = nullptr;
    const float* W = nullptr;
    const float* b = nullptr;
    const float* lin_w = nullptr;
    const float* lin_b = nullptr;
    const int* edges = nullptr;
    const int* batch = nullptr;
    for (int i = 0; i < n_in; i++) {
        switch (in_sizes[i]) {
            case NN * DD:            x     = (const float*)d_in[i]; break; // 6,400,000
            case LL * RR * DD * DD:  W     = (const float*)d_in[i]; break; // 65,536
            case LL * RR * DD:       b     = (const float*)d_in[i]; break; // 512
            case DD * CC:            lin_w = (const float*)d_in[i]; break; // 1,024
            case CC:                 lin_b = (const float*)d_in[i]; break; // 8
            case RR * 2 * EE:        edges = (const int*)d_in[i];   break; // 3,200,000
            case NN:                 batch = (const int*)d_in[i];   break; // 50,000
            default: break;
        }
    }
    float* out = (float*)d_out;                   // [G, C]

    const int TB = 256;

    // normalization (recomputed every call; no caching)
    k_zero<<<(RR * NN + TB - 1) / TB, TB>>>();
    k_deg<<<(RR * EE + TB - 1) / TB, TB>>>(edges);
    k_inv<<<(RR * NN + TB - 1) / TB, TB>>>();

    const int gemm_grid = (NN + 63) / 64;
    const long long scat_threads = (long long)RR * EE * 32;
    const int scat_blocks = (int)((scat_threads + TB - 1) / TB);
    const int nd_blocks = (NN * DD + TB - 1) / TB;
    const int pool_blocks = (NN * (DD / 4) + TB - 1) / TB;

    for (int l = 0; l < LL; l++) {
        k_gemm<<<dim3(gemm_grid, RR), 256>>>(x, l > 0 ? 1 : 0,
                                             W + (size_t)l * RR * DD * DD);
        k_init_out<<<nd_blocks, TB>>>(b + (size_t)l * RR * DD);
        k_scatter<<<scat_blocks, TB>>>(edges);
        if (l < LL - 1) {
            k_relu<<<nd_blocks, TB>>>();
        }
    }

    k_pool<<<pool_blocks, TB>>>(batch);
    k_final<<<1, GG * CC>>>(lin_w, lin_b, out);
}

// round 7
// speedup vs baseline: 3.2289x; 1.2874x over previous
#include <cuda_runtime.h>
#include <cuda_bf16.h>

// Problem constants (fixed by dataset)
#define NN 50000
#define DD 128
#define EE 800000
#define RR 2
#define LL 2
#define GG 64
#define CC 8
#define NTOT (RR * NN)   // 100000 CSR rows (relation-major)

// Scratch (__device__ globals; never referenced from host code)
__device__ float g_deg[NTOT];
__device__ float g_inv[NTOT];
__device__ int   g_rowptr[NTOT + 1];
__device__ int   g_cursor[NTOT];
__device__ int2  g_csr[RR * EE];       // (src, norm-as-int)
__device__ float g_xw[RR * NN * DD];   // per-layer: xw for both relations
__device__ float g_out[NN * DD];       // layer-2 output (pooled)
__device__ float g_h[NN * DD];         // hidden after relu
__device__ float g_sums[GG * DD];
__device__ float g_cnt[GG];

__device__ __forceinline__ void red_add_v4(float* addr, float a, float b,
                                           float c, float d) {
    asm volatile("red.global.add.v4.f32 [%0], {%1, %2, %3, %4};"
                 :: "l"(addr), "f"(a), "f"(b), "f"(c), "f"(d) : "memory");
}

// ---------------------------------------------------------------------------
__global__ void k_zero() {
    int t = blockIdx.x * blockDim.x + threadIdx.x;
    if (t < NTOT) g_deg[t] = 0.f;
    if (t < GG * DD) g_sums[t] = 0.f;
    if (t < GG) g_cnt[t] = 0.f;
}

// degree count (dst side), per relation
__global__ void k_deg(const int* __restrict__ edges) {
    int t = blockIdx.x * blockDim.x + threadIdx.x;
    if (t >= RR * EE) return;
    int r = (t >= EE) ? 1 : 0;
    int e = t - r * EE;
    int dst = edges[r * 2 * EE + EE + e];
    atomicAdd(&g_deg[r * NN + dst], 1.f);
}

__global__ void k_inv() {
    int t = blockIdx.x * blockDim.x + threadIdx.x;
    if (t >= NTOT) return;
    g_inv[t] = rsqrtf(g_deg[t] + 1.f);
}

// single-block exclusive scan over g_deg -> g_rowptr / g_cursor
__global__ void k_scan() {
    __shared__ int s[1024];
    __shared__ int carry_s;
    const int tid = threadIdx.x;
    if (tid == 0) carry_s = 0;
    __syncthreads();
    const int nchunk = (NTOT + 1023) / 1024;
    for (int c = 0; c < nchunk; c++) {
        int i = c * 1024 + tid;
        int v = (i < NTOT) ? (int)g_deg[i] : 0;
        s[tid] = v;
        __syncthreads();
#pragma unroll
        for (int off = 1; off < 1024; off <<= 1) {
            int t = (tid >= off) ? s[tid - off] : 0;
            __syncthreads();
            s[tid] += t;
            __syncthreads();
        }
        int incl = s[tid];
        int excl = incl - v + carry_s;
        if (i < NTOT) { g_rowptr[i] = excl; g_cursor[i] = excl; }
        __syncthreads();
        if (tid == 1023) carry_s += incl;     // chunk total
        __syncthreads();
    }
    if (tid == 0) g_rowptr[NTOT] = carry_s;
}

// scatter edge records into CSR buckets; norm precomputed (layer-invariant)
__global__ void k_fill(const int* __restrict__ edges) {
    int t = blockIdx.x * blockDim.x + threadIdx.x;
    if (t >= RR * EE) return;
    int r = (t >= EE) ? 1 : 0;
    int e = t - r * EE;
    int src = edges[r * 2 * EE + e];
    int dst = edges[r * 2 * EE + EE + e];
    int row = r * NN + dst;
    int pos = atomicAdd(&g_cursor[row], 1);
    float norm = g_inv[r * NN + src] * g_inv[row];
    g_csr[pos] = make_int2(src, __float_as_int(norm));
}

// ---------------------------------------------------------------------------
// GEMM: XW[r] = A (N x 128) @ W[l,r] (128 x 128)
__global__ void k_gemm(const float* __restrict__ x_in, int use_h,
                       const float* __restrict__ Wl) {
    const float* __restrict__ A = use_h ? g_h : x_in;
    const int r = blockIdx.y;
    const float* __restrict__ Wr = Wl + r * DD * DD;
    float* __restrict__ out = g_xw + (size_t)r * NN * DD;
    const int row0 = blockIdx.x * 64;
    __shared__ float sA[64 * DD];
    const int tid = threadIdx.x;

#pragma unroll
    for (int i = 0; i < 32; i++) {
        int idx = tid + i * 256;
        int rr = idx >> 7, cc = idx & 127;
        int row = row0 + rr;
        sA[idx] = (row < NN) ? A[row * DD + cc] : 0.f;
    }
    __syncthreads();

    const int lane = tid & 31;
    const int w = tid >> 5;
    float4 acc[8];
#pragma unroll
    for (int i = 0; i < 8; i++) acc[i] = make_float4(0.f, 0.f, 0.f, 0.f);

    const float* __restrict__ wp = Wr + lane * 4;
#pragma unroll 4
    for (int k = 0; k < DD; k++) {
        float4 wv = *(const float4*)(wp + k * DD);
#pragma unroll
        for (int rr = 0; rr < 8; rr++) {
            float a = sA[(w * 8 + rr) * DD + k];
            acc[rr].x = fmaf(a, wv.x, acc[rr].x);
            acc[rr].y = fmaf(a, wv.y, acc[rr].y);
            acc[rr].z = fmaf(a, wv.z, acc[rr].z);
            acc[rr].w = fmaf(a, wv.w, acc[rr].w);
        }
    }
#pragma unroll
    for (int rr = 0; rr < 8; rr++) {
        int row = row0 + w * 8 + rr;
        if (row < NN)
            *(float4*)&out[row * DD + lane * 4] = acc[rr];
    }
}

// ---------------------------------------------------------------------------
// CSR gather: warp per node, lane owns 4 cols. Fuses self-loop + biases +
// both relations' edge aggregation + optional ReLU. One write per output.
__global__ void k_gather(const float* __restrict__ bvec, int store_relu) {
    int gw = (blockIdx.x * blockDim.x + threadIdx.x) >> 5;
    if (gw >= NN) return;
    const int lane = threadIdx.x & 31;
    const int n = gw;
    const int c = lane * 4;

    float4 b0 = *(const float4*)&bvec[c];
    float4 b1 = *(const float4*)&bvec[DD + c];
    float i0 = g_inv[n];
    float i1 = g_inv[NN + n];
    float4 x0 = *(const float4*)&g_xw[(size_t)n * DD + c];
    float4 x1 = *(const float4*)&g_xw[(size_t)(NN + n) * DD + c];

    float4 acc;
    acc.x = b0.x + b1.x + x0.x * i0 * i0 + x1.x * i1 * i1;
    acc.y = b0.y + b1.y + x0.y * i0 * i0 + x1.y * i1 * i1;
    acc.z = b0.z + b1.z + x0.z * i0 * i0 + x1.z * i1 * i1;
    acc.w = b0.w + b1.w + x0.w * i0 * i0 + x1.w * i1 * i1;

#pragma unroll
    for (int r = 0; r < RR; r++) {
        const float* __restrict__ xw = g_xw + (size_t)r * NN * DD;
        int row = r * NN + n;
        int s0 = g_rowptr[row];
        int s1 = g_rowptr[row + 1];
#pragma unroll 2
        for (int j = s0; j < s1; j++) {
            int2 ed = __ldg(&g_csr[j]);
            float norm = __int_as_float(ed.y);
            float4 v = *(const float4*)&xw[(size_t)ed.x * DD + c];
            acc.x = fmaf(v.x, norm, acc.x);
            acc.y = fmaf(v.y, norm, acc.y);
            acc.z = fmaf(v.z, norm, acc.z);
            acc.w = fmaf(v.w, norm, acc.w);
        }
    }

    float* dst = store_relu ? g_h : g_out;
    if (store_relu) {
        acc.x = fmaxf(acc.x, 0.f); acc.y = fmaxf(acc.y, 0.f);
        acc.z = fmaxf(acc.z, 0.f); acc.w = fmaxf(acc.w, 0.f);
    }
    *(float4*)&dst[(size_t)n * DD + c] = acc;
}

// ---------------------------------------------------------------------------
// global mean pool: v4 reductions, 4 floats per thread
__global__ void k_pool(const int* __restrict__ batch) {
    int t = blockIdx.x * blockDim.x + threadIdx.x;
    if (t >= NN * (DD / 4)) return;
    int n = t >> 5;
    int c4 = (t & 31) * 4;
    int g = batch[n];
    float4 v = *(const float4*)&g_out[(size_t)n * DD + c4];
    red_add_v4(&g_sums[g * DD + c4], v.x, v.y, v.z, v.w);
    if (c4 == 0) atomicAdd(&g_cnt[g], 1.f);
}

__global__ void k_final(const float* __restrict__ lw, const float* __restrict__ lb,
                        float* __restrict__ out) {
    int t = threadIdx.x;          // 512 = G*C
    int g = t >> 3, c = t & 7;
    float inv = 1.f / fmaxf(g_cnt[g], 1.f);
    float acc = lb[c];
#pragma unroll 8
    for (int d = 0; d < DD; d++)
        acc = fmaf(g_sums[g * DD + d] * inv, lw[d * CC + c], acc);
    out[g * CC + c] = acc;
}

// ---------------------------------------------------------------------------
extern "C" void kernel_launch(void* const* d_in, const int* in_sizes, int n_in,
                              void* d_out, int out_size) {
    // Bind inputs by UNIQUE element counts (robust to metadata ordering)
    const float* x = nullptr;
    const float* W = nullptr;
    const float* b = nullptr;
    const float* lin_w = nullptr;
    const float* lin_b = nullptr;
    const int* edges = nullptr;
    const int* batch = nullptr;
    for (int i = 0; i < n_in; i++) {
        switch (in_sizes[i]) {
            case NN * DD:            x     = (const float*)d_in[i]; break;
            case LL * RR * DD * DD:  W     = (const float*)d_in[i]; break;
            case LL * RR * DD:       b     = (const float*)d_in[i]; break;
            case DD * CC:            lin_w = (const float*)d_in[i]; break;
            case CC:                 lin_b = (const float*)d_in[i]; break;
            case RR * 2 * EE:        edges = (const int*)d_in[i];   break;
            case NN:                 batch = (const int*)d_in[i];   break;
            default: break;
        }
    }
    float* out = (float*)d_out;                   // [G, C]

    const int TB = 256;

    // CSR build (recomputed every call; graph is layer-invariant)
    k_zero<<<(NTOT + TB - 1) / TB, TB>>>();
    k_deg<<<(RR * EE + TB - 1) / TB, TB>>>(edges);
    k_inv<<<(NTOT + TB - 1) / TB, TB>>>();
    k_scan<<<1, 1024>>>();
    k_fill<<<(RR * EE + TB - 1) / TB, TB>>>(edges);

    const int gemm_grid = (NN + 63) / 64;
    const int gath_blocks = (NN * 32 + TB - 1) / TB;
    const int pool_blocks = (NN * (DD / 4) + TB - 1) / TB;

    for (int l = 0; l < LL; l++) {
        k_gemm<<<dim3(gemm_grid, RR), 256>>>(x, l > 0 ? 1 : 0,
                                             W + (size_t)l * RR * DD * DD);
        k_gather<<<gath_blocks, TB>>>(b + (size_t)l * RR * DD,
                                      (l < LL - 1) ? 1 : 0);
    }

    k_pool<<<pool_blocks, TB>>>(batch);
    k_final<<<1, GG * CC>>>(lin_w, lin_b, out);
}

// round 8
// speedup vs baseline: 4.0480x; 1.2537x over previous
#include <cuda_runtime.h>
#include <cuda_bf16.h>

// Problem constants (fixed by dataset)
#define NN 50000
#define DD 128
#define EE 800000
#define RR 2
#define LL 2
#define GG 64
#define CC 8
#define NTOT (RR * NN)                 // 100000 CSR rows (relation-major)
#define NBLK ((NTOT + 1023) / 1024)    // 98 scan blocks

// Scratch (__device__ globals; never referenced from host code)
__device__ float g_deg[NTOT];
__device__ float g_inv[NTOT];
__device__ int   g_rowptr[NTOT + 1];
__device__ int   g_cursor[NTOT];
__device__ int   g_bsum[NBLK];
__device__ int   g_boff[NBLK];
__device__ int2  g_csr[RR * EE];       // (src, norm-as-int)
__device__ float g_xw[RR * NN * DD];   // per-layer: xw for both relations
__device__ float g_out[NN * DD];       // layer-2 output (pooled)
__device__ float g_h[NN * DD];         // hidden after relu
__device__ float g_sums[GG * DD];
__device__ float g_cnt[GG];

__device__ __forceinline__ void red_add_v4(float* addr, float a, float b,
                                           float c, float d) {
    asm volatile("red.global.add.v4.f32 [%0], {%1, %2, %3, %4};"
                 :: "l"(addr), "f"(a), "f"(b), "f"(c), "f"(d) : "memory");
}

// ---------------------------------------------------------------------------
__global__ void k_zero() {
    int t = blockIdx.x * blockDim.x + threadIdx.x;
    if (t < NTOT) g_deg[t] = 0.f;
    if (t < GG * DD) g_sums[t] = 0.f;
    if (t < GG) g_cnt[t] = 0.f;
}

// degree count (dst side), per relation
__global__ void k_deg(const int* __restrict__ edges) {
    int t = blockIdx.x * blockDim.x + threadIdx.x;
    if (t >= RR * EE) return;
    int r = (t >= EE) ? 1 : 0;
    int e = t - r * EE;
    int dst = edges[r * 2 * EE + EE + e];
    atomicAdd(&g_deg[r * NN + dst], 1.f);
}

__global__ void k_inv() {
    int t = blockIdx.x * blockDim.x + threadIdx.x;
    if (t >= NTOT) return;
    g_inv[t] = rsqrtf(g_deg[t] + 1.f);
}

// ---------------------------------------------------------------------------
// multi-block scan, phase 1: per-block warp-shuffle scan (1024 threads/block)
__global__ void k_scan1() {
    __shared__ int wsum[32];
    int i = blockIdx.x * 1024 + threadIdx.x;
    int v = (i < NTOT) ? (int)g_deg[i] : 0;
    int lane = threadIdx.x & 31, w = threadIdx.x >> 5;
    int s = v;
#pragma unroll
    for (int o = 1; o < 32; o <<= 1) {
        int t = __shfl_up_sync(0xffffffffu, s, o);
        if (lane >= o) s += t;
    }
    if (lane == 31) wsum[w] = s;
    __syncthreads();
    if (w == 0) {
        int ws = wsum[lane];
#pragma unroll
        for (int o = 1; o < 32; o <<= 1) {
            int t = __shfl_up_sync(0xffffffffu, ws, o);
            if (lane >= o) ws += t;
        }
        wsum[lane] = ws;
    }
    __syncthreads();
    int excl = s - v + (w > 0 ? wsum[w - 1] : 0);
    if (i < NTOT) g_rowptr[i] = excl;
    if (threadIdx.x == 1023) g_bsum[blockIdx.x] = wsum[31];
}

// phase 2: single block (128 threads) scans the 98 block totals
__global__ void k_scan2() {
    __shared__ int wsum[4];
    int lane = threadIdx.x & 31, w = threadIdx.x >> 5;
    int v = (threadIdx.x < NBLK) ? g_bsum[threadIdx.x] : 0;
    int s = v;
#pragma unroll
    for (int o = 1; o < 32; o <<= 1) {
        int t = __shfl_up_sync(0xffffffffu, s, o);
        if (lane >= o) s += t;
    }
    if (lane == 31) wsum[w] = s;
    __syncthreads();
    int base = 0;
    for (int k = 0; k < w; k++) base += wsum[k];
    if (threadIdx.x < NBLK) g_boff[threadIdx.x] = base + s - v;
    if (threadIdx.x == 0) g_rowptr[NTOT] = RR * EE;   // total is statically known
}

// phase 3: add block offsets
__global__ void k_scan3() {
    int i = blockIdx.x * blockDim.x + threadIdx.x;
    if (i >= NTOT) return;
    int val = g_rowptr[i] + g_boff[i >> 10];
    g_rowptr[i] = val;
    g_cursor[i] = val;
}

// scatter edge records into CSR buckets; norm precomputed (layer-invariant)
__global__ void k_fill(const int* __restrict__ edges) {
    int t = blockIdx.x * blockDim.x + threadIdx.x;
    if (t >= RR * EE) return;
    int r = (t >= EE) ? 1 : 0;
    int e = t - r * EE;
    int src = edges[r * 2 * EE + e];
    int dst = edges[r * 2 * EE + EE + e];
    int row = r * NN + dst;
    int pos = atomicAdd(&g_cursor[row], 1);
    float norm = g_inv[r * NN + src] * g_inv[row];
    g_csr[pos] = make_int2(src, __float_as_int(norm));
}

// ---------------------------------------------------------------------------
// GEMM: XW[r] = A (N x 128) @ W[l,r] (128 x 128)
__global__ void k_gemm(const float* __restrict__ x_in, int use_h,
                       const float* __restrict__ Wl) {
    const float* __restrict__ A = use_h ? g_h : x_in;
    const int r = blockIdx.y;
    const float* __restrict__ Wr = Wl + r * DD * DD;
    float* __restrict__ out = g_xw + (size_t)r * NN * DD;
    const int row0 = blockIdx.x * 64;
    __shared__ float sA[64 * DD];
    const int tid = threadIdx.x;

#pragma unroll
    for (int i = 0; i < 32; i++) {
        int idx = tid + i * 256;
        int rr = idx >> 7, cc = idx & 127;
        int row = row0 + rr;
        sA[idx] = (row < NN) ? A[row * DD + cc] : 0.f;
    }
    __syncthreads();

    const int lane = tid & 31;
    const int w = tid >> 5;
    float4 acc[8];
#pragma unroll
    for (int i = 0; i < 8; i++) acc[i] = make_float4(0.f, 0.f, 0.f, 0.f);

    const float* __restrict__ wp = Wr + lane * 4;
#pragma unroll 4
    for (int k = 0; k < DD; k++) {
        float4 wv = *(const float4*)(wp + k * DD);
#pragma unroll
        for (int rr = 0; rr < 8; rr++) {
            float a = sA[(w * 8 + rr) * DD + k];
            acc[rr].x = fmaf(a, wv.x, acc[rr].x);
            acc[rr].y = fmaf(a, wv.y, acc[rr].y);
            acc[rr].z = fmaf(a, wv.z, acc[rr].z);
            acc[rr].w = fmaf(a, wv.w, acc[rr].w);
        }
    }
#pragma unroll
    for (int rr = 0; rr < 8; rr++) {
        int row = row0 + w * 8 + rr;
        if (row < NN)
            *(float4*)&out[row * DD + lane * 4] = acc[rr];
    }
}

// ---------------------------------------------------------------------------
// CSR gather: warp per node, lane owns 4 cols. Fuses self-loop + biases +
// both relations' edge aggregation + optional ReLU. One write per output.
__global__ void k_gather(const float* __restrict__ bvec, int store_relu) {
    int gw = (blockIdx.x * blockDim.x + threadIdx.x) >> 5;
    if (gw >= NN) return;
    const int lane = threadIdx.x & 31;
    const int n = gw;
    const int c = lane * 4;

    float4 b0 = *(const float4*)&bvec[c];
    float4 b1 = *(const float4*)&bvec[DD + c];
    float i0 = g_inv[n];
    float i1 = g_inv[NN + n];
    float4 x0 = *(const float4*)&g_xw[(size_t)n * DD + c];
    float4 x1 = *(const float4*)&g_xw[(size_t)(NN + n) * DD + c];

    float4 acc;
    acc.x = b0.x + b1.x + x0.x * i0 * i0 + x1.x * i1 * i1;
    acc.y = b0.y + b1.y + x0.y * i0 * i0 + x1.y * i1 * i1;
    acc.z = b0.z + b1.z + x0.z * i0 * i0 + x1.z * i1 * i1;
    acc.w = b0.w + b1.w + x0.w * i0 * i0 + x1.w * i1 * i1;

#pragma unroll
    for (int r = 0; r < RR; r++) {
        const float* __restrict__ xw = g_xw + (size_t)r * NN * DD;
        int row = r * NN + n;
        int s0 = g_rowptr[row];
        int s1 = g_rowptr[row + 1];
#pragma unroll 2
        for (int j = s0; j < s1; j++) {
            int2 ed = __ldg(&g_csr[j]);
            float norm = __int_as_float(ed.y);
            float4 v = *(const float4*)&xw[(size_t)ed.x * DD + c];
            acc.x = fmaf(v.x, norm, acc.x);
            acc.y = fmaf(v.y, norm, acc.y);
            acc.z = fmaf(v.z, norm, acc.z);
            acc.w = fmaf(v.w, norm, acc.w);
        }
    }

    float* dst = store_relu ? g_h : g_out;
    if (store_relu) {
        acc.x = fmaxf(acc.x, 0.f); acc.y = fmaxf(acc.y, 0.f);
        acc.z = fmaxf(acc.z, 0.f); acc.w = fmaxf(acc.w, 0.f);
    }
    *(float4*)&dst[(size_t)n * DD + c] = acc;
}

// ---------------------------------------------------------------------------
// global mean pool: v4 reductions, 4 floats per thread
__global__ void k_pool(const int* __restrict__ batch) {
    int t = blockIdx.x * blockDim.x + threadIdx.x;
    if (t >= NN * (DD / 4)) return;
    int n = t >> 5;
    int c4 = (t & 31) * 4;
    int g = batch[n];
    float4 v = *(const float4*)&g_out[(size_t)n * DD + c4];
    red_add_v4(&g_sums[g * DD + c4], v.x, v.y, v.z, v.w);
    if (c4 == 0) atomicAdd(&g_cnt[g], 1.f);
}

__global__ void k_final(const float* __restrict__ lw, const float* __restrict__ lb,
                        float* __restrict__ out) {
    int t = threadIdx.x;          // 512 = G*C
    int g = t >> 3, c = t & 7;
    float inv = 1.f / fmaxf(g_cnt[g], 1.f);
    float acc = lb[c];
#pragma unroll 8
    for (int d = 0; d < DD; d++)
        acc = fmaf(g_sums[g * DD + d] * inv, lw[d * CC + c], acc);
    out[g * CC + c] = acc;
}

// ---------------------------------------------------------------------------
extern "C" void kernel_launch(void* const* d_in, const int* in_sizes, int n_in,
                              void* d_out, int out_size) {
    // Bind inputs by UNIQUE element counts (robust to metadata ordering)
    const float* x = nullptr;
    const float* W = nullptr;
    const float* b = nullptr;
    const float* lin_w = nullptr;
    const float* lin_b = nullptr;
    const int* edges = nullptr;
    const int* batch = nullptr;
    for (int i = 0; i < n_in; i++) {
        switch (in_sizes[i]) {
            case NN * DD:            x     = (const float*)d_in[i]; break;
            case LL * RR * DD * DD:  W     = (const float*)d_in[i]; break;
            case LL * RR * DD:       b     = (const float*)d_in[i]; break;
            case DD * CC:            lin_w = (const float*)d_in[i]; break;
            case CC:                 lin_b = (const float*)d_in[i]; break;
            case RR * 2 * EE:        edges = (const int*)d_in[i];   break;
            case NN:                 batch = (const int*)d_in[i];   break;
            default: break;
        }
    }
    float* out = (float*)d_out;                   // [G, C]

    const int TB = 256;

    // CSR build (recomputed every call; graph is layer-invariant)
    k_zero<<<(NTOT + TB - 1) / TB, TB>>>();
    k_deg<<<(RR * EE + TB - 1) / TB, TB>>>(edges);
    k_inv<<<(NTOT + TB - 1) / TB, TB>>>();
    k_scan1<<<NBLK, 1024>>>();
    k_scan2<<<1, 128>>>();
    k_scan3<<<(NTOT + TB - 1) / TB, TB>>>();
    k_fill<<<(RR * EE + TB - 1) / TB, TB>>>(edges);

    const int gemm_grid = (NN + 63) / 64;
    const int gath_blocks = (NN * 32 + TB - 1) / TB;
    const int pool_blocks = (NN * (DD / 4) + TB - 1) / TB;

    for (int l = 0; l < LL; l++) {
        k_gemm<<<dim3(gemm_grid, RR), 256>>>(x, l > 0 ? 1 : 0,
                                             W + (size_t)l * RR * DD * DD);
        k_gather<<<gath_blocks, TB>>>(b + (size_t)l * RR * DD,
                                      (l < LL - 1) ? 1 : 0);
    }

    k_pool<<<pool_blocks, TB>>>(batch);
    k_final<<<1, GG * CC>>>(lin_w, lin_b, out);
}

// round 10
// speedup vs baseline: 4.8679x; 1.2025x over previous
#include <cuda_runtime.h>
#include <cuda_bf16.h>

// Problem constants (fixed by dataset)
#define NN 50000
#define DD 128
#define EE 800000
#define RR 2
#define LL 2
#define GG 64
#define CC 8
#define NTOT (RR * NN)                 // 100000 CSR rows (relation-major)
#define NBLK ((NTOT + 1023) / 1024)    // 98 scan blocks

// Scratch (__device__ globals; never referenced from host code)
__device__ float g_deg[NTOT];
__device__ float g_inv[NTOT];
__device__ int   g_rowptr[NTOT + 1];
__device__ int   g_cursor[NTOT];
__device__ int   g_bsum[NBLK];
__device__ int   g_boff[NBLK];
__device__ int2  g_csr[RR * EE];       // (src, norm-as-int)
__device__ float g_xw[RR * NN * DD];   // per-layer: xw for both relations
__device__ float g_out[NN * DD];       // layer-2 output (pooled)
__device__ float g_h[NN * DD];         // hidden after relu
__device__ float g_sums[GG * DD];
__device__ float g_cnt[GG];

__device__ __forceinline__ void red_add_v4(float* addr, float a, float b,
                                           float c, float d) {
    asm volatile("red.global.add.v4.f32 [%0], {%1, %2, %3, %4};"
                 :: "l"(addr), "f"(a), "f"(b), "f"(c), "f"(d) : "memory");
}

// ---------------------------------------------------------------------------
__global__ void k_zero() {
    int t = blockIdx.x * blockDim.x + threadIdx.x;
    if (t < NTOT) g_deg[t] = 0.f;
    if (t < GG * DD) g_sums[t] = 0.f;
    if (t < GG) g_cnt[t] = 0.f;
}

// degree count (dst side), per relation
__global__ void k_deg(const int* __restrict__ edges) {
    int t = blockIdx.x * blockDim.x + threadIdx.x;
    if (t >= RR * EE) return;
    int r = (t >= EE) ? 1 : 0;
    int e = t - r * EE;
    int dst = edges[r * 2 * EE + EE + e];
    atomicAdd(&g_deg[r * NN + dst], 1.f);
}

__global__ void k_inv() {
    int t = blockIdx.x * blockDim.x + threadIdx.x;
    if (t >= NTOT) return;
    g_inv[t] = rsqrtf(g_deg[t] + 1.f);
}

// ---------------------------------------------------------------------------
// multi-block scan, phase 1: per-block warp-shuffle scan (1024 threads/block)
__global__ void k_scan1() {
    __shared__ int wsum[32];
    int i = blockIdx.x * 1024 + threadIdx.x;
    int v = (i < NTOT) ? (int)g_deg[i] : 0;
    int lane = threadIdx.x & 31, w = threadIdx.x >> 5;
    int s = v;
#pragma unroll
    for (int o = 1; o < 32; o <<= 1) {
        int t = __shfl_up_sync(0xffffffffu, s, o);
        if (lane >= o) s += t;
    }
    if (lane == 31) wsum[w] = s;
    __syncthreads();
    if (w == 0) {
        int ws = wsum[lane];
#pragma unroll
        for (int o = 1; o < 32; o <<= 1) {
            int t = __shfl_up_sync(0xffffffffu, ws, o);
            if (lane >= o) ws += t;
        }
        wsum[lane] = ws;
    }
    __syncthreads();
    int excl = s - v + (w > 0 ? wsum[w - 1] : 0);
    if (i < NTOT) g_rowptr[i] = excl;
    if (threadIdx.x == 1023) g_bsum[blockIdx.x] = wsum[31];
}

// phase 2: single block (128 threads) scans the 98 block totals
__global__ void k_scan2() {
    __shared__ int wsum[4];
    int lane = threadIdx.x & 31, w = threadIdx.x >> 5;
    int v = (threadIdx.x < NBLK) ? g_bsum[threadIdx.x] : 0;
    int s = v;
#pragma unroll
    for (int o = 1; o < 32; o <<= 1) {
        int t = __shfl_up_sync(0xffffffffu, s, o);
        if (lane >= o) s += t;
    }
    if (lane == 31) wsum[w] = s;
    __syncthreads();
    int base = 0;
    for (int k = 0; k < w; k++) base += wsum[k];
    if (threadIdx.x < NBLK) g_boff[threadIdx.x] = base + s - v;
    if (threadIdx.x == 0) g_rowptr[NTOT] = RR * EE;   // total statically known
}

// phase 3: add block offsets
__global__ void k_scan3() {
    int i = blockIdx.x * blockDim.x + threadIdx.x;
    if (i >= NTOT) return;
    int val = g_rowptr[i] + g_boff[i >> 10];
    g_rowptr[i] = val;
    g_cursor[i] = val;
}

// scatter edge records into CSR buckets; norm precomputed (layer-invariant)
__global__ void k_fill(const int* __restrict__ edges) {
    int t = blockIdx.x * blockDim.x + threadIdx.x;
    if (t >= RR * EE) return;
    int r = (t >= EE) ? 1 : 0;
    int e = t - r * EE;
    int src = edges[r * 2 * EE + e];
    int dst = edges[r * 2 * EE + EE + e];
    int row = r * NN + dst;
    int pos = atomicAdd(&g_cursor[row], 1);
    float norm = g_inv[r * NN + src] * g_inv[row];
    g_csr[pos] = make_int2(src, __float_as_int(norm));
}

// ---------------------------------------------------------------------------
// GEMM: XW[r] = A (N x 128) @ W[l,r] (128 x 128)
// __launch_bounds__(256,3): cap regs at 85 -> 3 CTAs/SM (occ 37%) for
// latency hiding; FFMA issue is the binding resource.
__global__ void __launch_bounds__(256, 3)
k_gemm(const float* __restrict__ x_in, int use_h, const float* __restrict__ Wl) {
    const float* __restrict__ A = use_h ? g_h : x_in;
    const int r = blockIdx.y;
    const float* __restrict__ Wr = Wl + r * DD * DD;
    float* __restrict__ out = g_xw + (size_t)r * NN * DD;
    const int row0 = blockIdx.x * 64;
    __shared__ float sA[64 * DD];
    const int tid = threadIdx.x;

#pragma unroll
    for (int i = 0; i < 32; i++) {
        int idx = tid + i * 256;
        int rr = idx >> 7, cc = idx & 127;
        int row = row0 + rr;
        sA[idx] = (row < NN) ? A[row * DD + cc] : 0.f;
    }
    __syncthreads();

    const int lane = tid & 31;
    const int w = tid >> 5;
    float4 acc[8];
#pragma unroll
    for (int i = 0; i < 8; i++) acc[i] = make_float4(0.f, 0.f, 0.f, 0.f);

    const float* __restrict__ wp = Wr + lane * 4;
#pragma unroll 8
    for (int k = 0; k < DD; k++) {
        float4 wv = *(const float4*)(wp + k * DD);
#pragma unroll
        for (int rr = 0; rr < 8; rr++) {
            float a = sA[(w * 8 + rr) * DD + k];
            acc[rr].x = fmaf(a, wv.x, acc[rr].x);
            acc[rr].y = fmaf(a, wv.y, acc[rr].y);
            acc[rr].z = fmaf(a, wv.z, acc[rr].z);
            acc[rr].w = fmaf(a, wv.w, acc[rr].w);
        }
    }
#pragma unroll
    for (int rr = 0; rr < 8; rr++) {
        int row = row0 + w * 8 + rr;
        if (row < NN)
            *(float4*)&out[row * DD + lane * 4] = acc[rr];
    }
}

// ---------------------------------------------------------------------------
// CSR gather: warp per node, lane owns 4 cols. Fuses self-loop + biases +
// both relations' edge aggregation + optional ReLU. One write per output.
__global__ void k_gather(const float* __restrict__ bvec, int store_relu) {
    int gw = (blockIdx.x * blockDim.x + threadIdx.x) >> 5;
    if (gw >= NN) return;
    const int lane = threadIdx.x & 31;
    const int n = gw;
    const int c = lane * 4;

    float4 b0 = *(const float4*)&bvec[c];
    float4 b1 = *(const float4*)&bvec[DD + c];
    float i0 = g_inv[n];
    float i1 = g_inv[NN + n];
    float4 x0 = *(const float4*)&g_xw[(size_t)n * DD + c];
    float4 x1 = *(const float4*)&g_xw[(size_t)(NN + n) * DD + c];

    float4 acc;
    acc.x = b0.x + b1.x + x0.x * i0 * i0 + x1.x * i1 * i1;
    acc.y = b0.y + b1.y + x0.y * i0 * i0 + x1.y * i1 * i1;
    acc.z = b0.z + b1.z + x0.z * i0 * i0 + x1.z * i1 * i1;
    acc.w = b0.w + b1.w + x0.w * i0 * i0 + x1.w * i1 * i1;

#pragma unroll
    for (int r = 0; r < RR; r++) {
        const float* __restrict__ xw = g_xw + (size_t)r * NN * DD;
        int row = r * NN + n;
        int s0 = g_rowptr[row];
        int s1 = g_rowptr[row + 1];
#pragma unroll 2
        for (int j = s0; j < s1; j++) {
            int2 ed = __ldg(&g_csr[j]);
            float norm = __int_as_float(ed.y);
            float4 v = *(const float4*)&xw[(size_t)ed.x * DD + c];
            acc.x = fmaf(v.x, norm, acc.x);
            acc.y = fmaf(v.y, norm, acc.y);
            acc.z = fmaf(v.z, norm, acc.z);
            acc.w = fmaf(v.w, norm, acc.w);
        }
    }

    float* dst = store_relu ? g_h : g_out;
    if (store_relu) {
        acc.x = fmaxf(acc.x, 0.f); acc.y = fmaxf(acc.y, 0.f);
        acc.z = fmaxf(acc.z, 0.f); acc.w = fmaxf(acc.w, 0.f);
    }
    *(float4*)&dst[(size_t)n * DD + c] = acc;
}

// ---------------------------------------------------------------------------
// global mean pool: v4 reductions, 4 floats per thread
__global__ void k_pool(const int* __restrict__ batch) {
    int t = blockIdx.x * blockDim.x + threadIdx.x;
    if (t >= NN * (DD / 4)) return;
    int n = t >> 5;
    int c4 = (t & 31) * 4;
    int g = batch[n];
    float4 v = *(const float4*)&g_out[(size_t)n * DD + c4];
    red_add_v4(&g_sums[g * DD + c4], v.x, v.y, v.z, v.w);
    if (c4 == 0) atomicAdd(&g_cnt[g], 1.f);
}

__global__ void k_final(const float* __restrict__ lw, const float* __restrict__ lb,
                        float* __restrict__ out) {
    int t = threadIdx.x;          // 512 = G*C
    int g = t >> 3, c = t & 7;
    float inv = 1.f / fmaxf(g_cnt[g], 1.f);
    float acc = lb[c];
#pragma unroll 8
    for (int d = 0; d < DD; d++)
        acc = fmaf(g_sums[g * DD + d] * inv, lw[d * CC + c], acc);
    out[g * CC + c] = acc;
}

// ---------------------------------------------------------------------------
extern "C" void kernel_launch(void* const* d_in, const int* in_sizes, int n_in,
                              void* d_out, int out_size) {
    // Bind inputs by UNIQUE element counts (robust to metadata ordering)
    const float* x = nullptr;
    const float* W = nullptr;
    const float* b = nullptr;
    const float* lin_w = nullptr;
    const float* lin_b = nullptr;
    const int* edges = nullptr;
    const int* batch = nullptr;
    for (int i = 0; i < n_in; i++) {
        switch (in_sizes[i]) {
            case NN * DD:            x     = (const float*)d_in[i]; break;
            case LL * RR * DD * DD:  W     = (const float*)d_in[i]; break;
            case LL * RR * DD:       b     = (const float*)d_in[i]; break;
            case DD * CC:            lin_w = (const float*)d_in[i]; break;
            case CC:                 lin_b = (const float*)d_in[i]; break;
            case RR * 2 * EE:        edges = (const int*)d_in[i];   break;
            case NN:                 batch = (const int*)d_in[i];   break;
            default: break;
        }
    }
    float* out = (float*)d_out;                   // [G, C]

    const int TB = 256;

    // CSR build (recomputed every call; graph is layer-invariant)
    k_zero<<<(NTOT + TB - 1) / TB, TB>>>();
    k_deg<<<(RR * EE + TB - 1) / TB, TB>>>(edges);
    k_inv<<<(NTOT + TB - 1) / TB, TB>>>();
    k_scan1<<<NBLK, 1024>>>();
    k_scan2<<<1, 128>>>();
    k_scan3<<<(NTOT + TB - 1) / TB, TB>>>();
    k_fill<<<(RR * EE + TB - 1) / TB, TB>>>(edges);

    const int gemm_grid = (NN + 63) / 64;
    const int gath_blocks = (NN * 32 + TB - 1) / TB;
    const int pool_blocks = (NN * (DD / 4) + TB - 1) / TB;

    for (int l = 0; l < LL; l++) {
        k_gemm<<<dim3(gemm_grid, RR), 256>>>(x, l > 0 ? 1 : 0,
                                             W + (size_t)l * RR * DD * DD);
        k_gather<<<gath_blocks, TB>>>(b + (size_t)l * RR * DD,
                                      (l < LL - 1) ? 1 : 0);
    }

    k_pool<<<pool_blocks, TB>>>(batch);
    k_final<<<1, GG * CC>>>(lin_w, lin_b, out);
}